// round 1
// baseline (speedup 1.0000x reference)
#include <cuda_runtime.h>
#include <cuda_bf16.h>
#include <cstdint>

// Problem constants (match reference_code)
#define NUM_USERS 100000
#define NUM_ITEMS 50000
#define LATENT    64
#define N_EDGES   600000
#define BATCH     4096
#define N_NODES   (NUM_USERS + NUM_ITEMS)          // 150000
#define TOT_F     (N_NODES * LATENT)               // 9,600,000 floats
#define USER_F    (NUM_USERS * LATENT)             // 6,400,000 floats

// ---------------- scratch (device globals; no allocations allowed) ----------
__device__ float g_bufA[TOT_F];
__device__ float g_bufB[TOT_F];
__device__ float g_acc [TOT_F];
__device__ float g_deg [N_NODES];
__device__ float g_inv [N_NODES];
__device__ float g_w   [N_EDGES];

// ---------------- vectorized no-return reduction (sm_90+) -------------------
__device__ __forceinline__ void red4(float* p, float4 v) {
    asm volatile("red.global.add.v4.f32 [%0], {%1,%2,%3,%4};"
                 :: "l"(p), "f"(v.x), "f"(v.y), "f"(v.z), "f"(v.w)
                 : "memory");
}

// ---------------- kernels ---------------------------------------------------

// Build x0 into bufA, acc = x0, bufB = 0, deg = 0.  float4 over TOT_F/4 elems.
__global__ void k_init(const float* __restrict__ uemb,
                       const float* __restrict__ iemb) {
    int i = blockIdx.x * blockDim.x + threadIdx.x;          // float4 index
    const int n4 = TOT_F / 4;
    if (i < n4) {
        int base = i * 4;
        float4 v;
        if (base < USER_F) {
            v = *reinterpret_cast<const float4*>(uemb + base);
        } else {
            v = *reinterpret_cast<const float4*>(iemb + (base - USER_F));
        }
        reinterpret_cast<float4*>(g_bufA)[i] = v;
        reinterpret_cast<float4*>(g_acc )[i] = v;
        reinterpret_cast<float4*>(g_bufB)[i] = make_float4(0.f, 0.f, 0.f, 0.f);
    }
    if (i < N_NODES) g_deg[i] = 0.f;
}

// Degree count: each undirected edge increments both endpoints.
__global__ void k_deg(const int* __restrict__ eu, const int* __restrict__ ei) {
    int e = blockIdx.x * blockDim.x + threadIdx.x;
    if (e < N_EDGES) {
        atomicAdd(&g_deg[eu[e]], 1.0f);                // compiles to RED
        atomicAdd(&g_deg[NUM_USERS + ei[e]], 1.0f);
    }
}

// inv_sqrt per node
__global__ void k_inv() {
    int n = blockIdx.x * blockDim.x + threadIdx.x;
    if (n < N_NODES) {
        float d = g_deg[n];
        g_inv[n] = (d > 0.f) ? rsqrtf(d) : 0.f;
    }
}

// Symmetric edge weight  w = inv[u] * inv[item]
__global__ void k_w(const int* __restrict__ eu, const int* __restrict__ ei) {
    int e = blockIdx.x * blockDim.x + threadIdx.x;
    if (e < N_EDGES) {
        g_w[e] = g_inv[eu[e]] * g_inv[NUM_USERS + ei[e]];
    }
}

// SpMM scatter: for each undirected edge, item_row += w*x[u]; user_row += w*x[i].
// Half-warp (16 lanes) per edge; each lane owns one float4 (4 of 64 columns).
__global__ void k_spmm(const float* __restrict__ x, float* __restrict__ y,
                       const int* __restrict__ eu, const int* __restrict__ ei) {
    int gid  = blockIdx.x * blockDim.x + threadIdx.x;
    int e    = gid >> 4;            // edge index
    int sub  = gid & 15;            // float4 slot within the 64-col row
    if (e >= N_EDGES) return;

    int u = eu[e];
    int v = NUM_USERS + ei[e];
    float w = g_w[e];

    const float4* xu = reinterpret_cast<const float4*>(x + (size_t)u * LATENT) + sub;
    const float4* xv = reinterpret_cast<const float4*>(x + (size_t)v * LATENT) + sub;
    float4 a = *xu;
    float4 b = *xv;

    float4 wa = make_float4(w * a.x, w * a.y, w * a.z, w * a.w);
    float4 wb = make_float4(w * b.x, w * b.y, w * b.z, w * b.w);

    float* yv = const_cast<float*>(y) + (size_t)v * LATENT + sub * 4;
    float* yu = const_cast<float*>(y) + (size_t)u * LATENT + sub * 4;
    red4(yv, wa);     // item row accumulates from user
    red4(yu, wb);     // user row accumulates from item
}

// acc += src; zero_buf = 0   (fused streaming pass, float4)
__global__ void k_acc_zero(const float* __restrict__ src, float* __restrict__ zb) {
    int i = blockIdx.x * blockDim.x + threadIdx.x;
    const int n4 = TOT_F / 4;
    if (i >= n4) return;
    float4 a = reinterpret_cast<float4*>(g_acc)[i];
    float4 s = reinterpret_cast<const float4*>(src)[i];
    a.x += s.x; a.y += s.y; a.z += s.z; a.w += s.w;
    reinterpret_cast<float4*>(g_acc)[i] = a;
    reinterpret_cast<float4*>(zb)[i]    = make_float4(0.f, 0.f, 0.f, 0.f);
}

// Final batched dot: one warp per batch element; gamma = (accU . accI) / 25
__global__ void k_dot(const int* __restrict__ users, const int* __restrict__ items,
                      float* __restrict__ out) {
    int warp = (blockIdx.x * blockDim.x + threadIdx.x) >> 5;
    int lane = threadIdx.x & 31;
    if (warp >= BATCH) return;

    int u = users[warp];
    int it = NUM_USERS + items[warp];
    const float* pu = g_acc + (size_t)u  * LATENT;
    const float* pi = g_acc + (size_t)it * LATENT;

    float s = pu[lane] * pi[lane] + pu[lane + 32] * pi[lane + 32];
    #pragma unroll
    for (int off = 16; off > 0; off >>= 1)
        s += __shfl_xor_sync(0xffffffffu, s, off);

    if (lane == 0) out[warp] = s * (1.0f / 25.0f);
}

// ---------------- launch ----------------------------------------------------
extern "C" void kernel_launch(void* const* d_in, const int* in_sizes, int n_in,
                              void* d_out, int out_size) {
    const int*   users = (const int*)  d_in[0];
    const int*   items = (const int*)  d_in[1];
    const int*   eu    = (const int*)  d_in[2];
    const int*   ei    = (const int*)  d_in[3];
    const float* uemb  = (const float*)d_in[4];
    const float* iemb  = (const float*)d_in[5];
    float*       out   = (float*)d_out;

    const int T = 256;
    const int n4      = TOT_F / 4;                       // 2.4M
    const int gInit   = (n4 + T - 1) / T;
    const int gEdge   = (N_EDGES + T - 1) / T;
    const int gNode   = (N_NODES + T - 1) / T;
    const int gSpmm   = (N_EDGES * 16 + T - 1) / T;      // half-warp per edge
    const int gDot    = (BATCH * 32 + T - 1) / T;

    // pointers to device globals (resolved at compile time via device symbols
    // passed as kernel args using the globals directly inside kernels; for
    // ping-pong we need raw addresses — obtain once per launch, cheap & capture-safe)
    static float* pA = nullptr; static float* pB = nullptr;
    if (!pA) { cudaGetSymbolAddress((void**)&pA, g_bufA);
               cudaGetSymbolAddress((void**)&pB, g_bufB); }

    k_init<<<gInit, T>>>(uemb, iemb);
    k_deg <<<gEdge, T>>>(eu, ei);
    k_inv <<<gNode, T>>>();
    k_w   <<<gEdge, T>>>(eu, ei);

    // 4 LightGCN layers, ping-pong A<->B
    // layer 0: A -> B ; acc += B ; zero A
    k_spmm    <<<gSpmm, T>>>(pA, pB, eu, ei);
    k_acc_zero<<<gInit, T>>>(pB, pA);
    // layer 1: B -> A ; acc += A ; zero B
    k_spmm    <<<gSpmm, T>>>(pB, pA, eu, ei);
    k_acc_zero<<<gInit, T>>>(pA, pB);
    // layer 2: A -> B
    k_spmm    <<<gSpmm, T>>>(pA, pB, eu, ei);
    k_acc_zero<<<gInit, T>>>(pB, pA);
    // layer 3: B -> A
    k_spmm    <<<gSpmm, T>>>(pB, pA, eu, ei);
    k_acc_zero<<<gInit, T>>>(pA, pB);

    k_dot<<<gDot, T>>>(users, items, out);
}

// round 2
// speedup vs baseline: 1.4601x; 1.4601x over previous
#include <cuda_runtime.h>
#include <cuda_bf16.h>
#include <cstdint>

// Problem constants (match reference_code)
#define NUM_USERS 100000
#define NUM_ITEMS 50000
#define LATENT    64
#define N_EDGES   600000
#define BATCH     4096
#define N_NODES   (NUM_USERS + NUM_ITEMS)          // 150000
#define TOT_F     (N_NODES * LATENT)               // 9,600,000 floats
#define USER_F    (NUM_USERS * LATENT)
#define N_DIR     (2 * N_EDGES)                    // 1.2M directed edges
#define N_PART    ((N_NODES + 255) / 256)          // 586 scan partials

// ---------------- scratch (device globals; no allocations allowed) ----------
__device__ float g_bufA[TOT_F];
__device__ float g_bufB[TOT_F];
__device__ int   g_degi  [N_NODES];
__device__ float g_inv   [N_NODES];
__device__ int   g_part  [N_PART];
__device__ int   g_poff  [N_PART];
__device__ int   g_rowptr[N_NODES];
__device__ int   g_cursor[N_NODES];
__device__ int2  g_adjw  [N_DIR];                  // (src_idx, w as float bits)
__device__ float g_s     [2 * BATCH * LATENT];     // running sums: users then items

// ---------------- kernels ---------------------------------------------------

// bufA = x0 = [user_emb ; item_emb]; degi = 0
__global__ void k_init(const float* __restrict__ uemb,
                       const float* __restrict__ iemb) {
    int i = blockIdx.x * blockDim.x + threadIdx.x;          // float4 index
    const int n4 = TOT_F / 4;
    if (i < n4) {
        int base = i * 4;
        float4 v = (base < USER_F)
            ? *reinterpret_cast<const float4*>(uemb + base)
            : *reinterpret_cast<const float4*>(iemb + (base - USER_F));
        reinterpret_cast<float4*>(g_bufA)[i] = v;
    }
    if (i < N_NODES) g_degi[i] = 0;
}

// s[b] initialized with layer-0 embedding of the sampled row
__global__ void k_dotinit(const int* __restrict__ users, const int* __restrict__ items,
                          const float* __restrict__ uemb, const float* __restrict__ iemb) {
    int gid = blockIdx.x * blockDim.x + threadIdx.x;
    int b   = gid >> 4;
    int sub = gid & 15;
    if (b >= 2 * BATCH) return;
    const float* src = (b < BATCH)
        ? uemb + (size_t)users[b] * LATENT
        : iemb + (size_t)items[b - BATCH] * LATENT;
    reinterpret_cast<float4*>(g_s + (size_t)b * LATENT)[sub] =
        reinterpret_cast<const float4*>(src)[sub];
}

// Degree count (int REDs)
__global__ void k_deg(const int* __restrict__ eu, const int* __restrict__ ei) {
    int e = blockIdx.x * blockDim.x + threadIdx.x;
    if (e < N_EDGES) {
        atomicAdd(&g_degi[eu[e]], 1);
        atomicAdd(&g_degi[NUM_USERS + ei[e]], 1);
    }
}

__global__ void k_inv() {
    int n = blockIdx.x * blockDim.x + threadIdx.x;
    if (n < N_NODES) {
        int d = g_degi[n];
        g_inv[n] = (d > 0) ? rsqrtf((float)d) : 0.f;
    }
}

// per-256-chunk degree sums
__global__ void k_part() {
    __shared__ int s[256];
    int n = blockIdx.x * 256 + threadIdx.x;
    s[threadIdx.x] = (n < N_NODES) ? g_degi[n] : 0;
    __syncthreads();
    for (int off = 128; off > 0; off >>= 1) {
        if (threadIdx.x < off) s[threadIdx.x] += s[threadIdx.x + off];
        __syncthreads();
    }
    if (threadIdx.x == 0) g_part[blockIdx.x] = s[0];
}

// exclusive scan of the 586 partials (single block, Hillis-Steele over 1024)
__global__ void k_scanpart() {
    __shared__ int s[1024];
    int t = threadIdx.x;
    int v = (t < N_PART) ? g_part[t] : 0;
    s[t] = v;
    __syncthreads();
    for (int off = 1; off < 1024; off <<= 1) {
        int a = (t >= off) ? s[t - off] : 0;
        __syncthreads();
        s[t] += a;
        __syncthreads();
    }
    if (t < N_PART) g_poff[t] = s[t] - v;   // exclusive
}

// rowptr = poff[chunk] + exclusive-scan within chunk; cursor = rowptr
__global__ void k_rowptr() {
    __shared__ int s[256];
    int t = threadIdx.x;
    int n = blockIdx.x * 256 + t;
    int v = (n < N_NODES) ? g_degi[n] : 0;
    s[t] = v;
    __syncthreads();
    for (int off = 1; off < 256; off <<= 1) {
        int a = (t >= off) ? s[t - off] : 0;
        __syncthreads();
        s[t] += a;
        __syncthreads();
    }
    if (n < N_NODES) {
        int rp = g_poff[blockIdx.x] + s[t] - v;
        g_rowptr[n] = rp;
        g_cursor[n] = rp;
    }
}

// Fill CSR adjacency: each undirected edge contributes to both rows
__global__ void k_fill(const int* __restrict__ eu, const int* __restrict__ ei) {
    int e = blockIdx.x * blockDim.x + threadIdx.x;
    if (e >= N_EDGES) return;
    int u = eu[e];
    int v = NUM_USERS + ei[e];
    float w = g_inv[u] * g_inv[v];
    int wb = __float_as_int(w);
    int pu = atomicAdd(&g_cursor[u], 1);
    int pv = atomicAdd(&g_cursor[v], 1);
    g_adjw[pu] = make_int2(v, wb);
    g_adjw[pv] = make_int2(u, wb);
}

// Gather SpMM: half-warp (16 lanes) per destination row, lane owns one float4
__global__ void k_spmm_csr(const float* __restrict__ x, float* __restrict__ y) {
    int gid = blockIdx.x * blockDim.x + threadIdx.x;
    int row = gid >> 4;
    int sub = gid & 15;
    if (row >= N_NODES) return;

    int beg = g_rowptr[row];
    int cnt = g_degi[row];
    float4 acc = make_float4(0.f, 0.f, 0.f, 0.f);

    int j = 0;
    for (; j + 1 < cnt; j += 2) {                     // 2x unroll for MLP
        int2 a0 = g_adjw[beg + j];
        int2 a1 = g_adjw[beg + j + 1];
        float w0 = __int_as_float(a0.y);
        float w1 = __int_as_float(a1.y);
        float4 v0 = reinterpret_cast<const float4*>(x + (size_t)a0.x * LATENT)[sub];
        float4 v1 = reinterpret_cast<const float4*>(x + (size_t)a1.x * LATENT)[sub];
        acc.x += w0 * v0.x + w1 * v1.x;
        acc.y += w0 * v0.y + w1 * v1.y;
        acc.z += w0 * v0.z + w1 * v1.z;
        acc.w += w0 * v0.w + w1 * v1.w;
    }
    if (j < cnt) {
        int2 a0 = g_adjw[beg + j];
        float w0 = __int_as_float(a0.y);
        float4 v0 = reinterpret_cast<const float4*>(x + (size_t)a0.x * LATENT)[sub];
        acc.x += w0 * v0.x;
        acc.y += w0 * v0.y;
        acc.z += w0 * v0.z;
        acc.w += w0 * v0.w;
    }
    reinterpret_cast<float4*>(y + (size_t)row * LATENT)[sub] = acc;
}

// s[b] += x[row_b]   (tiny: 8192 rows)
__global__ void k_batch_acc(const float* __restrict__ x,
                            const int* __restrict__ users, const int* __restrict__ items) {
    int gid = blockIdx.x * blockDim.x + threadIdx.x;
    int b   = gid >> 4;
    int sub = gid & 15;
    if (b >= 2 * BATCH) return;
    int row = (b < BATCH) ? users[b] : NUM_USERS + items[b - BATCH];
    float4 v = reinterpret_cast<const float4*>(x + (size_t)row * LATENT)[sub];
    float4* dst = reinterpret_cast<float4*>(g_s + (size_t)b * LATENT) + sub;
    float4 a = *dst;
    a.x += v.x; a.y += v.y; a.z += v.z; a.w += v.w;
    *dst = a;
}

// gamma[b] = (su[b] . si[b]) / 25     (mean over 5 layer snapshots, both sides)
__global__ void k_dot(float* __restrict__ out) {
    int warp = (blockIdx.x * blockDim.x + threadIdx.x) >> 5;
    int lane = threadIdx.x & 31;
    if (warp >= BATCH) return;
    const float* pu = g_s + (size_t)warp * LATENT;
    const float* pi = g_s + (size_t)(BATCH + warp) * LATENT;
    float s = pu[lane] * pi[lane] + pu[lane + 32] * pi[lane + 32];
    #pragma unroll
    for (int off = 16; off > 0; off >>= 1)
        s += __shfl_xor_sync(0xffffffffu, s, off);
    if (lane == 0) out[warp] = s * (1.0f / 25.0f);
}

// ---------------- launch ----------------------------------------------------
extern "C" void kernel_launch(void* const* d_in, const int* in_sizes, int n_in,
                              void* d_out, int out_size) {
    const int*   users = (const int*)  d_in[0];
    const int*   items = (const int*)  d_in[1];
    const int*   eu    = (const int*)  d_in[2];
    const int*   ei    = (const int*)  d_in[3];
    const float* uemb  = (const float*)d_in[4];
    const float* iemb  = (const float*)d_in[5];
    float*       out   = (float*)d_out;

    const int T = 256;
    const int n4     = TOT_F / 4;
    const int gInit  = (n4 + T - 1) / T;
    const int gEdge  = (N_EDGES + T - 1) / T;
    const int gNode  = (N_NODES + T - 1) / T;
    const int gRow16 = (N_NODES * 16 + T - 1) / T;
    const int gB16   = (2 * BATCH * 16 + T - 1) / T;
    const int gDot   = (BATCH * 32 + T - 1) / T;

    static float* pA = nullptr; static float* pB = nullptr;
    if (!pA) { cudaGetSymbolAddress((void**)&pA, g_bufA);
               cudaGetSymbolAddress((void**)&pB, g_bufB); }

    // setup
    k_init    <<<gInit, T>>>(uemb, iemb);
    k_dotinit <<<gB16,  T>>>(users, items, uemb, iemb);
    k_deg     <<<gEdge, T>>>(eu, ei);
    k_inv     <<<gNode, T>>>();
    k_part    <<<N_PART, 256>>>();
    k_scanpart<<<1, 1024>>>();
    k_rowptr  <<<N_PART, 256>>>();
    k_fill    <<<gEdge, T>>>(eu, ei);

    // 4 LightGCN layers (gather, ping-pong, no zeroing / no atomics)
    k_spmm_csr <<<gRow16, T>>>(pA, pB);
    k_batch_acc<<<gB16,   T>>>(pB, users, items);
    k_spmm_csr <<<gRow16, T>>>(pB, pA);
    k_batch_acc<<<gB16,   T>>>(pA, users, items);
    k_spmm_csr <<<gRow16, T>>>(pA, pB);
    k_batch_acc<<<gB16,   T>>>(pB, users, items);
    k_spmm_csr <<<gRow16, T>>>(pB, pA);
    k_batch_acc<<<gB16,   T>>>(pA, users, items);

    k_dot<<<gDot, T>>>(out);
}

// round 4
// speedup vs baseline: 1.8252x; 1.2500x over previous
#include <cuda_runtime.h>
#include <cuda_bf16.h>
#include <cstdint>

#define NUM_USERS 100000
#define NUM_ITEMS 50000
#define LATENT    64
#define N_EDGES   600000
#define BATCH     4096
#define N_NODES   (NUM_USERS + NUM_ITEMS)          // 150000
#define TOT_F     (N_NODES * LATENT)               // 9,600,000 floats
#define N_DIR     (2 * N_EDGES)
#define N_PART    ((N_NODES + 255) / 256)          // 586

// ---------------- scratch (device globals) ----------------------------------
__device__ float g_z[4 * TOT_F];                   // z_1..z_4 (153.6 MB)
__device__ int   g_degi  [N_NODES];
__device__ float g_inv   [N_NODES];                // 1/sqrt(deg)  (0 if deg=0)
__device__ float g_inv2  [N_NODES];                // 1/deg        (0 if deg=0)
__device__ int   g_part  [N_PART];
__device__ int   g_poff  [N_PART];
__device__ int   g_rowptr[N_NODES];
__device__ int   g_cursor[N_NODES];
__device__ int   g_adj   [N_DIR];                  // src index only

// ---------------- kernels ---------------------------------------------------

__global__ void k_zero_deg() {
    int n = blockIdx.x * blockDim.x + threadIdx.x;
    if (n < N_NODES) g_degi[n] = 0;
}

__global__ void k_deg(const int* __restrict__ eu, const int* __restrict__ ei) {
    int e = blockIdx.x * blockDim.x + threadIdx.x;
    if (e < N_EDGES) {
        atomicAdd(&g_degi[eu[e]], 1);
        atomicAdd(&g_degi[NUM_USERS + ei[e]], 1);
    }
}

// inv / inv2 per node + per-256-chunk degree partial sums (fused)
__global__ void k_inv_part() {
    __shared__ int s[256];
    int t = threadIdx.x;
    int n = blockIdx.x * 256 + t;
    int d = (n < N_NODES) ? g_degi[n] : 0;
    if (n < N_NODES) {
        float fd = (float)d;
        g_inv [n] = (d > 0) ? rsqrtf(fd)  : 0.f;
        g_inv2[n] = (d > 0) ? (1.0f / fd) : 0.f;
    }
    s[t] = d;
    __syncthreads();
    for (int off = 128; off > 0; off >>= 1) {
        if (t < off) s[t] += s[t + off];
        __syncthreads();
    }
    if (t == 0) g_part[blockIdx.x] = s[0];
}

// exclusive scan of 586 partials (one block)
__global__ void k_scanpart() {
    __shared__ int s[1024];
    int t = threadIdx.x;
    int v = (t < N_PART) ? g_part[t] : 0;
    s[t] = v;
    __syncthreads();
    for (int off = 1; off < 1024; off <<= 1) {
        int a = (t >= off) ? s[t - off] : 0;
        __syncthreads();
        s[t] += a;
        __syncthreads();
    }
    if (t < N_PART) g_poff[t] = s[t] - v;
}

__global__ void k_rowptr() {
    __shared__ int s[256];
    int t = threadIdx.x;
    int n = blockIdx.x * 256 + t;
    int v = (n < N_NODES) ? g_degi[n] : 0;
    s[t] = v;
    __syncthreads();
    for (int off = 1; off < 256; off <<= 1) {
        int a = (t >= off) ? s[t - off] : 0;
        __syncthreads();
        s[t] += a;
        __syncthreads();
    }
    if (n < N_NODES) {
        int rp = g_poff[blockIdx.x] + s[t] - v;
        g_rowptr[n] = rp;
        g_cursor[n] = rp;
    }
}

__global__ void k_fill(const int* __restrict__ eu, const int* __restrict__ ei) {
    int e = blockIdx.x * blockDim.x + threadIdx.x;
    if (e >= N_EDGES) return;
    int u = eu[e];
    int v = NUM_USERS + ei[e];
    int pu = atomicAdd(&g_cursor[u], 1);
    int pv = atomicAdd(&g_cursor[v], 1);
    g_adj[pu] = v;
    g_adj[pv] = u;
}

// Layer 1: z1[dst] = inv2[dst] * sum_src inv[src] * x0[src]
// x0 read directly from input embeddings. Half-warp per row, lane = one float4.
__global__ void k_spmm1(const float* __restrict__ uemb, const float* __restrict__ iemb,
                        float* __restrict__ y) {
    int gid = blockIdx.x * blockDim.x + threadIdx.x;
    int row = gid >> 4;
    int sub = gid & 15;
    if (row >= N_NODES) return;

    int beg = g_rowptr[row];
    int cnt = g_degi[row];
    float4 acc = make_float4(0.f, 0.f, 0.f, 0.f);

    for (int j = 0; j < cnt; j++) {
        int src = g_adj[beg + j];
        float ws = g_inv[src];
        const float4* xp = (src < NUM_USERS)
            ? reinterpret_cast<const float4*>(uemb + (size_t)src * LATENT)
            : reinterpret_cast<const float4*>(iemb + (size_t)(src - NUM_USERS) * LATENT);
        float4 v = xp[sub];
        acc.x += ws * v.x; acc.y += ws * v.y; acc.z += ws * v.z; acc.w += ws * v.w;
    }
    float s = g_inv2[row];
    acc.x *= s; acc.y *= s; acc.z *= s; acc.w *= s;
    reinterpret_cast<float4*>(y + (size_t)row * LATENT)[sub] = acc;
}

// Layers 2..4: z_{l+1}[dst] = inv2[dst] * sum_src z_l[src]   (pure gather)
__global__ void k_spmmN(const float* __restrict__ x, float* __restrict__ y) {
    int gid = blockIdx.x * blockDim.x + threadIdx.x;
    int row = gid >> 4;
    int sub = gid & 15;
    if (row >= N_NODES) return;

    int beg = g_rowptr[row];
    int cnt = g_degi[row];
    float4 acc = make_float4(0.f, 0.f, 0.f, 0.f);

    int j = 0;
    for (; j + 3 < cnt; j += 4) {                  // 4x unroll for MLP
        int s0 = g_adj[beg + j + 0];
        int s1 = g_adj[beg + j + 1];
        int s2 = g_adj[beg + j + 2];
        int s3 = g_adj[beg + j + 3];
        float4 v0 = reinterpret_cast<const float4*>(x + (size_t)s0 * LATENT)[sub];
        float4 v1 = reinterpret_cast<const float4*>(x + (size_t)s1 * LATENT)[sub];
        float4 v2 = reinterpret_cast<const float4*>(x + (size_t)s2 * LATENT)[sub];
        float4 v3 = reinterpret_cast<const float4*>(x + (size_t)s3 * LATENT)[sub];
        acc.x += (v0.x + v1.x) + (v2.x + v3.x);
        acc.y += (v0.y + v1.y) + (v2.y + v3.y);
        acc.z += (v0.z + v1.z) + (v2.z + v3.z);
        acc.w += (v0.w + v1.w) + (v2.w + v3.w);
    }
    for (; j < cnt; j++) {
        int s0 = g_adj[beg + j];
        float4 v0 = reinterpret_cast<const float4*>(x + (size_t)s0 * LATENT)[sub];
        acc.x += v0.x; acc.y += v0.y; acc.z += v0.z; acc.w += v0.w;
    }
    float s = g_inv2[row];
    acc.x *= s; acc.y *= s; acc.z *= s; acc.w *= s;
    reinterpret_cast<float4*>(y + (size_t)row * LATENT)[sub] = acc;
}

// Final: per batch pair, su = x0_u + sqrt(deg_u)*(z1+z2+z3+z4)[u] (elementwise),
// same for item; gamma = su.si / 25.   One warp per pair, 2 floats per lane.
__global__ void k_final(const int* __restrict__ users, const int* __restrict__ items,
                        const float* __restrict__ uemb, const float* __restrict__ iemb,
                        const float* __restrict__ z1, const float* __restrict__ z2,
                        const float* __restrict__ z3, const float* __restrict__ z4,
                        float* __restrict__ out) {
    int warp = (blockIdx.x * blockDim.x + threadIdx.x) >> 5;
    int lane = threadIdx.x & 31;
    if (warp >= BATCH) return;

    int u  = users[warp];
    int it = NUM_USERS + items[warp];

    int du = g_degi[u];
    int di = g_degi[it];
    float su_sc = (du > 0) ? sqrtf((float)du) : 0.f;
    float si_sc = (di > 0) ? sqrtf((float)di) : 0.f;

    size_t ou = (size_t)u  * LATENT;
    size_t oi = (size_t)it * LATENT;

    float dot = 0.f;
    #pragma unroll
    for (int h = 0; h < 2; h++) {
        int c = lane + 32 * h;
        float eu0 = uemb[(size_t)u * LATENT + c];
        float ei0 = iemb[(size_t)(it - NUM_USERS) * LATENT + c];
        float zu  = z1[ou + c] + z2[ou + c] + z3[ou + c] + z4[ou + c];
        float zi  = z1[oi + c] + z2[oi + c] + z3[oi + c] + z4[oi + c];
        float su  = eu0 + su_sc * zu;
        float si  = ei0 + si_sc * zi;
        dot += su * si;
    }
    #pragma unroll
    for (int off = 16; off > 0; off >>= 1)
        dot += __shfl_xor_sync(0xffffffffu, dot, off);
    if (lane == 0) out[warp] = dot * (1.0f / 25.0f);
}

// ---------------- launch ----------------------------------------------------
extern "C" void kernel_launch(void* const* d_in, const int* in_sizes, int n_in,
                              void* d_out, int out_size) {
    const int*   users = (const int*)  d_in[0];
    const int*   items = (const int*)  d_in[1];
    const int*   eu    = (const int*)  d_in[2];
    const int*   ei    = (const int*)  d_in[3];
    const float* uemb  = (const float*)d_in[4];
    const float* iemb  = (const float*)d_in[5];
    float*       out   = (float*)d_out;

    const int T = 256;
    const int gEdge  = (N_EDGES + T - 1) / T;
    const int gNode  = (N_NODES + T - 1) / T;
    const int gRow16 = (N_NODES * 16 + T - 1) / T;
    const int gDot   = (BATCH * 32 + T - 1) / T;

    static float* pZ = nullptr;
    if (!pZ) cudaGetSymbolAddress((void**)&pZ, g_z);
    float* z1 = pZ;
    float* z2 = pZ + (size_t)TOT_F;
    float* z3 = pZ + (size_t)2 * TOT_F;
    float* z4 = pZ + (size_t)3 * TOT_F;

    // CSR build
    k_zero_deg<<<gNode, T>>>();
    k_deg     <<<gEdge, T>>>(eu, ei);
    k_inv_part<<<N_PART, 256>>>();
    k_scanpart<<<1, 1024>>>();
    k_rowptr  <<<N_PART, 256>>>();
    k_fill    <<<gEdge, T>>>(eu, ei);

    // 4 LightGCN layers in z-space
    k_spmm1<<<gRow16, T>>>(uemb, iemb, z1);
    k_spmmN<<<gRow16, T>>>(z1, z2);
    k_spmmN<<<gRow16, T>>>(z2, z3);
    k_spmmN<<<gRow16, T>>>(z3, z4);

    // final gather + dot
    k_final<<<gDot, T>>>(users, items, uemb, iemb, z1, z2, z3, z4, out);
}

// round 6
// speedup vs baseline: 2.3003x; 1.2603x over previous
#include <cuda_runtime.h>
#include <cuda_bf16.h>
#include <cuda_fp16.h>
#include <cstdint>

#define NUM_USERS 100000
#define NUM_ITEMS 50000
#define LATENT    64
#define N_EDGES   600000
#define BATCH     4096
#define N_NODES   (NUM_USERS + NUM_ITEMS)          // 150000
#define TOT_F     (N_NODES * LATENT)               // 9,600,000
#define N_DIR     (2 * N_EDGES)
#define N_PART    ((N_NODES + 255) / 256)          // 586

// ---------------- scratch (device globals) ----------------------------------
__device__ __half g_z[4 * TOT_F];                  // z_1..z_4 fp16 (76.8 MB)
__device__ int    g_degi  [N_NODES];
__device__ float  g_inv   [N_NODES];               // 1/sqrt(deg)
__device__ float  g_inv2  [N_NODES];               // 1/deg
__device__ int    g_part  [N_PART];
__device__ int    g_rowptr[N_NODES];
__device__ int    g_cursor[N_NODES];
__device__ int    g_adj   [N_DIR];                 // src index only

// ---------------- kernels ---------------------------------------------------

__global__ void k_zero_deg() {
    int n = blockIdx.x * blockDim.x + threadIdx.x;
    if (n < N_NODES) g_degi[n] = 0;
}

__global__ void k_deg(const int* __restrict__ eu, const int* __restrict__ ei) {
    int e = blockIdx.x * blockDim.x + threadIdx.x;
    if (e < N_EDGES) {
        atomicAdd(&g_degi[eu[e]], 1);
        atomicAdd(&g_degi[NUM_USERS + ei[e]], 1);
    }
}

// inv / inv2 per node + per-256-chunk degree partial sums (fused)
__global__ void k_inv_part() {
    __shared__ int s[256];
    int t = threadIdx.x;
    int n = blockIdx.x * 256 + t;
    int d = (n < N_NODES) ? g_degi[n] : 0;
    if (n < N_NODES) {
        float fd = (float)d;
        g_inv [n] = (d > 0) ? rsqrtf(fd)  : 0.f;
        g_inv2[n] = (d > 0) ? (1.0f / fd) : 0.f;
    }
    s[t] = d;
    __syncthreads();
    for (int off = 128; off > 0; off >>= 1) {
        if (t < off) s[t] += s[t + off];
        __syncthreads();
    }
    if (t == 0) g_part[blockIdx.x] = s[0];
}

// rowptr: each block redundantly sums partials before it (<=586 ints), then
// local 256-scan. Removes the separate serialized scan kernel.
__global__ void k_rowptr() {
    __shared__ int s[256];
    __shared__ int base_s;
    int t   = threadIdx.x;
    int bid = blockIdx.x;

    int p = 0;
    for (int i = t; i < bid; i += 256) p += g_part[i];
    s[t] = p;
    __syncthreads();
    for (int off = 128; off > 0; off >>= 1) {
        if (t < off) s[t] += s[t + off];
        __syncthreads();
    }
    if (t == 0) base_s = s[0];
    __syncthreads();
    int base = base_s;

    int n = bid * 256 + t;
    int v = (n < N_NODES) ? g_degi[n] : 0;
    s[t] = v;
    __syncthreads();
    for (int off = 1; off < 256; off <<= 1) {
        int a = (t >= off) ? s[t - off] : 0;
        __syncthreads();
        s[t] += a;
        __syncthreads();
    }
    if (n < N_NODES) {
        int rp = base + s[t] - v;
        g_rowptr[n] = rp;
        g_cursor[n] = rp;
    }
}

__global__ void k_fill(const int* __restrict__ eu, const int* __restrict__ ei) {
    int e = blockIdx.x * blockDim.x + threadIdx.x;
    if (e >= N_EDGES) return;
    int u = eu[e];
    int v = NUM_USERS + ei[e];
    int pu = atomicAdd(&g_cursor[u], 1);
    int pv = atomicAdd(&g_cursor[v], 1);
    g_adj[pu] = v;
    g_adj[pv] = u;
}

// Layer 1: z1[dst] = inv2[dst] * sum_src inv[src] * x0[src]   (fp32 in, fp16 out)
// Half-warp (16 lanes) per row; lane owns one float4 (4 cols), writes 4 halves.
__global__ void k_spmm1(const float* __restrict__ uemb, const float* __restrict__ iemb,
                        __half* __restrict__ y) {
    int gid = blockIdx.x * blockDim.x + threadIdx.x;
    int row = gid >> 4;
    int sub = gid & 15;
    if (row >= N_NODES) return;

    int beg = g_rowptr[row];
    int cnt = g_degi[row];
    float4 acc = make_float4(0.f, 0.f, 0.f, 0.f);

    for (int j = 0; j < cnt; j++) {
        int src = g_adj[beg + j];
        float ws = g_inv[src];
        const float4* xp = (src < NUM_USERS)
            ? reinterpret_cast<const float4*>(uemb + (size_t)src * LATENT)
            : reinterpret_cast<const float4*>(iemb + (size_t)(src - NUM_USERS) * LATENT);
        float4 v = xp[sub];
        acc.x += ws * v.x; acc.y += ws * v.y; acc.z += ws * v.z; acc.w += ws * v.w;
    }
    float s = g_inv2[row];
    __half2 h0 = __floats2half2_rn(acc.x * s, acc.y * s);
    __half2 h1 = __floats2half2_rn(acc.z * s, acc.w * s);
    uint2 pack;
    pack.x = *reinterpret_cast<unsigned*>(&h0);
    pack.y = *reinterpret_cast<unsigned*>(&h1);
    reinterpret_cast<uint2*>(y + (size_t)row * LATENT)[sub] = pack;
}

// Layers 2..4: z_{l+1}[dst] = inv2[dst] * sum_src z_l[src]   (fp16 in/out)
// 8 lanes per row; lane owns 8 halves (uint4 = 16B). fp32 accumulation.
__global__ void k_spmmN(const __half* __restrict__ x, __half* __restrict__ y) {
    int gid = blockIdx.x * blockDim.x + threadIdx.x;
    int row = gid >> 3;
    int sub = gid & 7;
    if (row >= N_NODES) return;

    int beg = g_rowptr[row];
    int cnt = g_degi[row];
    float acc[8] = {0.f, 0.f, 0.f, 0.f, 0.f, 0.f, 0.f, 0.f};

    auto accum = [&](uint4 v) {
        const __half2* h = reinterpret_cast<const __half2*>(&v);
        #pragma unroll
        for (int q = 0; q < 4; q++) {
            float2 f = __half22float2(h[q]);
            acc[2 * q]     += f.x;
            acc[2 * q + 1] += f.y;
        }
    };

    int j = 0;
    for (; j + 3 < cnt; j += 4) {                  // 4x unroll for MLP
        int s0 = g_adj[beg + j + 0];
        int s1 = g_adj[beg + j + 1];
        int s2 = g_adj[beg + j + 2];
        int s3 = g_adj[beg + j + 3];
        uint4 v0 = reinterpret_cast<const uint4*>(x + (size_t)s0 * LATENT)[sub];
        uint4 v1 = reinterpret_cast<const uint4*>(x + (size_t)s1 * LATENT)[sub];
        uint4 v2 = reinterpret_cast<const uint4*>(x + (size_t)s2 * LATENT)[sub];
        uint4 v3 = reinterpret_cast<const uint4*>(x + (size_t)s3 * LATENT)[sub];
        accum(v0); accum(v1); accum(v2); accum(v3);
    }
    for (; j < cnt; j++) {
        int s0 = g_adj[beg + j];
        uint4 v0 = reinterpret_cast<const uint4*>(x + (size_t)s0 * LATENT)[sub];
        accum(v0);
    }

    float s = g_inv2[row];
    uint4 outp;
    __half2* oh = reinterpret_cast<__half2*>(&outp);
    #pragma unroll
    for (int q = 0; q < 4; q++)
        oh[q] = __floats2half2_rn(acc[2 * q] * s, acc[2 * q + 1] * s);
    reinterpret_cast<uint4*>(y + (size_t)row * LATENT)[sub] = outp;
}

// Final: su = x0_u + sqrt(deg_u)*(z1+z2+z3+z4)[u]; gamma = su.si / 25.
__global__ void k_final(const int* __restrict__ users, const int* __restrict__ items,
                        const float* __restrict__ uemb, const float* __restrict__ iemb,
                        const __half* __restrict__ z1, const __half* __restrict__ z2,
                        const __half* __restrict__ z3, const __half* __restrict__ z4,
                        float* __restrict__ out) {
    int warp = (blockIdx.x * blockDim.x + threadIdx.x) >> 5;
    int lane = threadIdx.x & 31;
    if (warp >= BATCH) return;

    int u  = users[warp];
    int it = NUM_USERS + items[warp];

    int du = g_degi[u];
    int di = g_degi[it];
    float su_sc = (du > 0) ? sqrtf((float)du) : 0.f;
    float si_sc = (di > 0) ? sqrtf((float)di) : 0.f;

    size_t ou = (size_t)u  * LATENT;
    size_t oi = (size_t)it * LATENT;

    float dot = 0.f;
    #pragma unroll
    for (int h = 0; h < 2; h++) {
        int c = lane + 32 * h;
        float eu0 = uemb[(size_t)u * LATENT + c];
        float ei0 = iemb[(size_t)(it - NUM_USERS) * LATENT + c];
        float zu  = __half2float(z1[ou + c]) + __half2float(z2[ou + c])
                  + __half2float(z3[ou + c]) + __half2float(z4[ou + c]);
        float zi  = __half2float(z1[oi + c]) + __half2float(z2[oi + c])
                  + __half2float(z3[oi + c]) + __half2float(z4[oi + c]);
        float su  = eu0 + su_sc * zu;
        float si  = ei0 + si_sc * zi;
        dot += su * si;
    }
    #pragma unroll
    for (int off = 16; off > 0; off >>= 1)
        dot += __shfl_xor_sync(0xffffffffu, dot, off);
    if (lane == 0) out[warp] = dot * (1.0f / 25.0f);
}

// ---------------- launch ----------------------------------------------------
extern "C" void kernel_launch(void* const* d_in, const int* in_sizes, int n_in,
                              void* d_out, int out_size) {
    const int*   users = (const int*)  d_in[0];
    const int*   items = (const int*)  d_in[1];
    const int*   eu    = (const int*)  d_in[2];
    const int*   ei    = (const int*)  d_in[3];
    const float* uemb  = (const float*)d_in[4];
    const float* iemb  = (const float*)d_in[5];
    float*       out   = (float*)d_out;

    const int T = 256;
    const int gEdge  = (N_EDGES + T - 1) / T;
    const int gNode  = (N_NODES + T - 1) / T;
    const int gRow16 = (N_NODES * 16 + T - 1) / T;
    const int gRow8  = (N_NODES *  8 + T - 1) / T;
    const int gDot   = (BATCH * 32 + T - 1) / T;

    static __half* pZ = nullptr;
    if (!pZ) cudaGetSymbolAddress((void**)&pZ, g_z);
    __half* z1 = pZ;
    __half* z2 = pZ + (size_t)TOT_F;
    __half* z3 = pZ + (size_t)2 * TOT_F;
    __half* z4 = pZ + (size_t)3 * TOT_F;

    // CSR build
    k_zero_deg<<<gNode, T>>>();
    k_deg     <<<gEdge, T>>>(eu, ei);
    k_inv_part<<<N_PART, 256>>>();
    k_rowptr  <<<N_PART, 256>>>();
    k_fill    <<<gEdge, T>>>(eu, ei);

    // 4 LightGCN layers in z-space (fp16 storage, fp32 accumulation)
    k_spmm1<<<gRow16, T>>>(uemb, iemb, z1);
    k_spmmN<<<gRow8,  T>>>(z1, z2);
    k_spmmN<<<gRow8,  T>>>(z2, z3);
    k_spmmN<<<gRow8,  T>>>(z3, z4);

    // final gather + dot
    k_final<<<gDot, T>>>(users, items, uemb, iemb, z1, z2, z3, z4, out);
}

// round 7
// speedup vs baseline: 2.4581x; 1.0686x over previous
#include <cuda_runtime.h>
#include <cuda_bf16.h>
#include <cuda_fp16.h>
#include <cstdint>

#define NUM_USERS 100000
#define NUM_ITEMS 50000
#define LATENT    64
#define N_EDGES   600000
#define BATCH     4096
#define N_NODES   (NUM_USERS + NUM_ITEMS)          // 150000
#define TOT_F     (N_NODES * LATENT)               // 9,600,000
#define USER_F    (NUM_USERS * LATENT)
#define N_DIR     (2 * N_EDGES)
#define N_PART    ((N_NODES + 255) / 256)          // 586

// ---------------- scratch (device globals) ----------------------------------
__device__ __half g_x0h[TOT_F];                    // fp16 copy of x0 (19.2 MB)
__device__ __half g_z[4 * TOT_F];                  // z_1..z_4 fp16 (76.8 MB)
__device__ int    g_degi  [N_NODES];
__device__ float  g_inv   [N_NODES];               // 1/sqrt(deg)
__device__ float  g_inv2  [N_NODES];               // 1/deg
__device__ int    g_part  [N_PART];
__device__ int    g_rowptr[N_NODES];
__device__ int    g_cursor[N_NODES];
__device__ int    g_adj   [N_DIR];                 // src index only

// ---------------- kernels ---------------------------------------------------

// Fused: zero degi + cast x0 = [uemb; iemb] to fp16 (8 halves per thread)
__global__ void k_init_conv(const float* __restrict__ uemb,
                            const float* __restrict__ iemb) {
    int i = blockIdx.x * blockDim.x + threadIdx.x;   // 8-elem chunk index
    const int n8 = TOT_F / 8;
    if (i < n8) {
        int base = i * 8;
        const float4* src = (base < USER_F)
            ? reinterpret_cast<const float4*>(uemb + base)
            : reinterpret_cast<const float4*>(iemb + (base - USER_F));
        float4 a = src[0];
        float4 b = src[1];
        uint4 pack;
        __half2* h = reinterpret_cast<__half2*>(&pack);
        h[0] = __floats2half2_rn(a.x, a.y);
        h[1] = __floats2half2_rn(a.z, a.w);
        h[2] = __floats2half2_rn(b.x, b.y);
        h[3] = __floats2half2_rn(b.z, b.w);
        reinterpret_cast<uint4*>(g_x0h)[i] = pack;
    }
    if (i < N_NODES) g_degi[i] = 0;
}

__global__ void k_deg(const int* __restrict__ eu, const int* __restrict__ ei) {
    int e = blockIdx.x * blockDim.x + threadIdx.x;
    if (e < N_EDGES) {
        atomicAdd(&g_degi[eu[e]], 1);
        atomicAdd(&g_degi[NUM_USERS + ei[e]], 1);
    }
}

// inv / inv2 per node + per-256-chunk degree partial sums (fused)
__global__ void k_inv_part() {
    __shared__ int s[256];
    int t = threadIdx.x;
    int n = blockIdx.x * 256 + t;
    int d = (n < N_NODES) ? g_degi[n] : 0;
    if (n < N_NODES) {
        float fd = (float)d;
        g_inv [n] = (d > 0) ? rsqrtf(fd)  : 0.f;
        g_inv2[n] = (d > 0) ? (1.0f / fd) : 0.f;
    }
    s[t] = d;
    __syncthreads();
    for (int off = 128; off > 0; off >>= 1) {
        if (t < off) s[t] += s[t + off];
        __syncthreads();
    }
    if (t == 0) g_part[blockIdx.x] = s[0];
}

// rowptr: each block redundantly sums partials before it, then local 256-scan
__global__ void k_rowptr() {
    __shared__ int s[256];
    __shared__ int base_s;
    int t   = threadIdx.x;
    int bid = blockIdx.x;

    int p = 0;
    for (int i = t; i < bid; i += 256) p += g_part[i];
    s[t] = p;
    __syncthreads();
    for (int off = 128; off > 0; off >>= 1) {
        if (t < off) s[t] += s[t + off];
        __syncthreads();
    }
    if (t == 0) base_s = s[0];
    __syncthreads();
    int base = base_s;

    int n = bid * 256 + t;
    int v = (n < N_NODES) ? g_degi[n] : 0;
    s[t] = v;
    __syncthreads();
    for (int off = 1; off < 256; off <<= 1) {
        int a = (t >= off) ? s[t - off] : 0;
        __syncthreads();
        s[t] += a;
        __syncthreads();
    }
    if (n < N_NODES) {
        int rp = base + s[t] - v;
        g_rowptr[n] = rp;
        g_cursor[n] = rp;
    }
}

__global__ void k_fill(const int* __restrict__ eu, const int* __restrict__ ei) {
    int e = blockIdx.x * blockDim.x + threadIdx.x;
    if (e >= N_EDGES) return;
    int u = eu[e];
    int v = NUM_USERS + ei[e];
    int pu = atomicAdd(&g_cursor[u], 1);
    int pv = atomicAdd(&g_cursor[v], 1);
    g_adj[pu] = v;
    g_adj[pv] = u;
}

// Layer 1: z1[dst] = inv2[dst] * sum_src inv[src] * x0h[src]
// 8 lanes per row; lane owns 8 halves (uint4). fp32 accumulation.
__global__ void k_spmm1h(const __half* __restrict__ x, __half* __restrict__ y) {
    int gid = blockIdx.x * blockDim.x + threadIdx.x;
    int row = gid >> 3;
    int sub = gid & 7;
    if (row >= N_NODES) return;

    int beg = g_rowptr[row];
    int cnt = g_degi[row];
    float acc[8] = {0.f, 0.f, 0.f, 0.f, 0.f, 0.f, 0.f, 0.f};

    auto accum = [&](uint4 v, float ws) {
        const __half2* h = reinterpret_cast<const __half2*>(&v);
        #pragma unroll
        for (int q = 0; q < 4; q++) {
            float2 f = __half22float2(h[q]);
            acc[2 * q]     += ws * f.x;
            acc[2 * q + 1] += ws * f.y;
        }
    };

    int j = 0;
    for (; j + 1 < cnt; j += 2) {
        int s0 = g_adj[beg + j + 0];
        int s1 = g_adj[beg + j + 1];
        float w0 = g_inv[s0];
        float w1 = g_inv[s1];
        uint4 v0 = reinterpret_cast<const uint4*>(x + (size_t)s0 * LATENT)[sub];
        uint4 v1 = reinterpret_cast<const uint4*>(x + (size_t)s1 * LATENT)[sub];
        accum(v0, w0); accum(v1, w1);
    }
    if (j < cnt) {
        int s0 = g_adj[beg + j];
        float w0 = g_inv[s0];
        uint4 v0 = reinterpret_cast<const uint4*>(x + (size_t)s0 * LATENT)[sub];
        accum(v0, w0);
    }

    float s = g_inv2[row];
    uint4 outp;
    __half2* oh = reinterpret_cast<__half2*>(&outp);
    #pragma unroll
    for (int q = 0; q < 4; q++)
        oh[q] = __floats2half2_rn(acc[2 * q] * s, acc[2 * q + 1] * s);
    reinterpret_cast<uint4*>(y + (size_t)row * LATENT)[sub] = outp;
}

// Layers 2..4: z_{l+1}[dst] = inv2[dst] * sum_src z_l[src]   (fp16 in/out)
__global__ void k_spmmN(const __half* __restrict__ x, __half* __restrict__ y) {
    int gid = blockIdx.x * blockDim.x + threadIdx.x;
    int row = gid >> 3;
    int sub = gid & 7;
    if (row >= N_NODES) return;

    int beg = g_rowptr[row];
    int cnt = g_degi[row];
    float acc[8] = {0.f, 0.f, 0.f, 0.f, 0.f, 0.f, 0.f, 0.f};

    auto accum = [&](uint4 v) {
        const __half2* h = reinterpret_cast<const __half2*>(&v);
        #pragma unroll
        for (int q = 0; q < 4; q++) {
            float2 f = __half22float2(h[q]);
            acc[2 * q]     += f.x;
            acc[2 * q + 1] += f.y;
        }
    };

    int j = 0;
    for (; j + 3 < cnt; j += 4) {
        int s0 = g_adj[beg + j + 0];
        int s1 = g_adj[beg + j + 1];
        int s2 = g_adj[beg + j + 2];
        int s3 = g_adj[beg + j + 3];
        uint4 v0 = reinterpret_cast<const uint4*>(x + (size_t)s0 * LATENT)[sub];
        uint4 v1 = reinterpret_cast<const uint4*>(x + (size_t)s1 * LATENT)[sub];
        uint4 v2 = reinterpret_cast<const uint4*>(x + (size_t)s2 * LATENT)[sub];
        uint4 v3 = reinterpret_cast<const uint4*>(x + (size_t)s3 * LATENT)[sub];
        accum(v0); accum(v1); accum(v2); accum(v3);
    }
    for (; j < cnt; j++) {
        int s0 = g_adj[beg + j];
        uint4 v0 = reinterpret_cast<const uint4*>(x + (size_t)s0 * LATENT)[sub];
        accum(v0);
    }

    float s = g_inv2[row];
    uint4 outp;
    __half2* oh = reinterpret_cast<__half2*>(&outp);
    #pragma unroll
    for (int q = 0; q < 4; q++)
        oh[q] = __floats2half2_rn(acc[2 * q] * s, acc[2 * q + 1] * s);
    reinterpret_cast<uint4*>(y + (size_t)row * LATENT)[sub] = outp;
}

// Final: su = x0_u + sqrt(deg_u)*(z1+z2+z3+z4)[u]; gamma = su.si / 25.
__global__ void k_final(const int* __restrict__ users, const int* __restrict__ items,
                        const float* __restrict__ uemb, const float* __restrict__ iemb,
                        const __half* __restrict__ z1, const __half* __restrict__ z2,
                        const __half* __restrict__ z3, const __half* __restrict__ z4,
                        float* __restrict__ out) {
    int warp = (blockIdx.x * blockDim.x + threadIdx.x) >> 5;
    int lane = threadIdx.x & 31;
    if (warp >= BATCH) return;

    int u  = users[warp];
    int it = NUM_USERS + items[warp];

    int du = g_degi[u];
    int di = g_degi[it];
    float su_sc = (du > 0) ? sqrtf((float)du) : 0.f;
    float si_sc = (di > 0) ? sqrtf((float)di) : 0.f;

    size_t ou = (size_t)u  * LATENT;
    size_t oi = (size_t)it * LATENT;

    float dot = 0.f;
    #pragma unroll
    for (int h = 0; h < 2; h++) {
        int c = lane + 32 * h;
        float eu0 = uemb[(size_t)u * LATENT + c];
        float ei0 = iemb[(size_t)(it - NUM_USERS) * LATENT + c];
        float zu  = __half2float(z1[ou + c]) + __half2float(z2[ou + c])
                  + __half2float(z3[ou + c]) + __half2float(z4[ou + c]);
        float zi  = __half2float(z1[oi + c]) + __half2float(z2[oi + c])
                  + __half2float(z3[oi + c]) + __half2float(z4[oi + c]);
        float su  = eu0 + su_sc * zu;
        float si  = ei0 + si_sc * zi;
        dot += su * si;
    }
    #pragma unroll
    for (int off = 16; off > 0; off >>= 1)
        dot += __shfl_xor_sync(0xffffffffu, dot, off);
    if (lane == 0) out[warp] = dot * (1.0f / 25.0f);
}

// ---------------- launch ----------------------------------------------------
extern "C" void kernel_launch(void* const* d_in, const int* in_sizes, int n_in,
                              void* d_out, int out_size) {
    const int*   users = (const int*)  d_in[0];
    const int*   items = (const int*)  d_in[1];
    const int*   eu    = (const int*)  d_in[2];
    const int*   ei    = (const int*)  d_in[3];
    const float* uemb  = (const float*)d_in[4];
    const float* iemb  = (const float*)d_in[5];
    float*       out   = (float*)d_out;

    const int T = 256;
    const int n8     = TOT_F / 8;
    const int gConv  = (n8 + T - 1) / T;
    const int gEdge  = (N_EDGES + T - 1) / T;
    const int gRow8  = (N_NODES * 8 + T - 1) / T;
    const int gDot   = (BATCH * 32 + T - 1) / T;

    static __half* pZ = nullptr; static __half* pX = nullptr;
    if (!pZ) { cudaGetSymbolAddress((void**)&pZ, g_z);
               cudaGetSymbolAddress((void**)&pX, g_x0h); }
    __half* z1 = pZ;
    __half* z2 = pZ + (size_t)TOT_F;
    __half* z3 = pZ + (size_t)2 * TOT_F;
    __half* z4 = pZ + (size_t)3 * TOT_F;

    // setup: fp16 cast + CSR build
    k_init_conv<<<gConv, T>>>(uemb, iemb);
    k_deg      <<<gEdge, T>>>(eu, ei);
    k_inv_part <<<N_PART, 256>>>();
    k_rowptr   <<<N_PART, 256>>>();
    k_fill     <<<gEdge, T>>>(eu, ei);

    // 4 LightGCN layers in z-space (fp16 storage, fp32 accumulation)
    k_spmm1h<<<gRow8, T>>>(pX, z1);
    k_spmmN <<<gRow8, T>>>(z1, z2);
    k_spmmN <<<gRow8, T>>>(z2, z3);
    k_spmmN <<<gRow8, T>>>(z3, z4);

    // final gather + dot
    k_final<<<gDot, T>>>(users, items, uemb, iemb, z1, z2, z3, z4, out);
}

// round 8
// speedup vs baseline: 2.8586x; 1.1629x over previous
#include <cuda_runtime.h>
#include <cuda_bf16.h>
#include <cuda_fp16.h>
#include <cstdint>

#define NUM_USERS 100000
#define NUM_ITEMS 50000
#define LATENT    64
#define N_EDGES   600000
#define BATCH     4096
#define N_NODES   (NUM_USERS + NUM_ITEMS)          // 150000
#define TOT_F     (N_NODES * LATENT)               // 9,600,000
#define USER_F    (NUM_USERS * LATENT)
#define N_DIR     (2 * N_EDGES)
#define N_PART    ((N_NODES + 255) / 256)          // 586

// ---------------- scratch (device globals) ----------------------------------
__device__ __half g_x0h[TOT_F];                    // fp16 x0 (19.2 MB)
__device__ __half g_z[3 * TOT_F];                  // z_1..z_3 fp16 (57.6 MB)
__device__ int    g_degi  [N_NODES];               // zero at entry (reset by spmm1h)
__device__ float  g_inv   [N_NODES];               // 1/sqrt(deg)
__device__ float  g_inv2  [N_NODES];               // 1/deg
__device__ int    g_part  [N_PART];
__device__ int    g_rowptr[N_NODES + 1];           // +1 sentinel = N_DIR
__device__ int    g_cursor[N_NODES];
__device__ int    g_adj   [N_DIR];                 // src index only

// ---------------- kernels ---------------------------------------------------

// Fused: degree atomics (threads < N_EDGES) + fp16 cast of x0 (all 1.2M threads).
// Relies on g_degi == 0 at entry (loader zero-init on first call; k_spmm1h
// resets it each run for the next graph replay).
__global__ void k_deg_conv(const int* __restrict__ eu, const int* __restrict__ ei,
                           const float* __restrict__ uemb, const float* __restrict__ iemb) {
    int i = blockIdx.x * blockDim.x + threadIdx.x;   // 0 .. 1.2M-1
    const int n8 = TOT_F / 8;                        // 1,200,000
    if (i < n8) {
        int base = i * 8;
        const float4* src = (base < USER_F)
            ? reinterpret_cast<const float4*>(uemb + base)
            : reinterpret_cast<const float4*>(iemb + (base - USER_F));
        float4 a = src[0];
        float4 b = src[1];
        uint4 pack;
        __half2* h = reinterpret_cast<__half2*>(&pack);
        h[0] = __floats2half2_rn(a.x, a.y);
        h[1] = __floats2half2_rn(a.z, a.w);
        h[2] = __floats2half2_rn(b.x, b.y);
        h[3] = __floats2half2_rn(b.z, b.w);
        reinterpret_cast<uint4*>(g_x0h)[i] = pack;
    }
    if (i < N_EDGES) {
        atomicAdd(&g_degi[eu[i]], 1);
        atomicAdd(&g_degi[NUM_USERS + ei[i]], 1);
    }
}

// inv / inv2 per node + per-256-chunk degree partial sums (fused)
__global__ void k_inv_part() {
    __shared__ int s[256];
    int t = threadIdx.x;
    int n = blockIdx.x * 256 + t;
    int d = (n < N_NODES) ? g_degi[n] : 0;
    if (n < N_NODES) {
        float fd = (float)d;
        g_inv [n] = (d > 0) ? rsqrtf(fd)  : 0.f;
        g_inv2[n] = (d > 0) ? (1.0f / fd) : 0.f;
    }
    s[t] = d;
    __syncthreads();
    for (int off = 128; off > 0; off >>= 1) {
        if (t < off) s[t] += s[t + off];
        __syncthreads();
    }
    if (t == 0) g_part[blockIdx.x] = s[0];
}

// rowptr: block sums partials before it, then local 256-scan. Writes sentinel.
__global__ void k_rowptr() {
    __shared__ int s[256];
    __shared__ int base_s;
    int t   = threadIdx.x;
    int bid = blockIdx.x;

    int p = 0;
    for (int i = t; i < bid; i += 256) p += g_part[i];
    s[t] = p;
    __syncthreads();
    for (int off = 128; off > 0; off >>= 1) {
        if (t < off) s[t] += s[t + off];
        __syncthreads();
    }
    if (t == 0) base_s = s[0];
    __syncthreads();
    int base = base_s;

    int n = bid * 256 + t;
    int v = (n < N_NODES) ? g_degi[n] : 0;
    s[t] = v;
    __syncthreads();
    for (int off = 1; off < 256; off <<= 1) {
        int a = (t >= off) ? s[t - off] : 0;
        __syncthreads();
        s[t] += a;
        __syncthreads();
    }
    if (n < N_NODES) {
        int rp = base + s[t] - v;
        g_rowptr[n] = rp;
        g_cursor[n] = rp;
        if (n == N_NODES - 1) g_rowptr[N_NODES] = N_DIR;
    }
}

__global__ void k_fill(const int* __restrict__ eu, const int* __restrict__ ei) {
    int e = blockIdx.x * blockDim.x + threadIdx.x;
    if (e >= N_EDGES) return;
    int u = eu[e];
    int v = NUM_USERS + ei[e];
    int pu = atomicAdd(&g_cursor[u], 1);
    int pv = atomicAdd(&g_cursor[v], 1);
    g_adj[pu] = v;
    g_adj[pv] = u;
}

// Layer 1: z1[dst] = inv2[dst] * sum_src inv[src] * x0h[src]
// 8 lanes per row; lane owns 8 halves (uint4). fp32 accumulation.
// Also resets g_degi for the next graph replay.
__global__ void k_spmm1h(const __half* __restrict__ x, __half* __restrict__ y) {
    int gid = blockIdx.x * blockDim.x + threadIdx.x;
    if (gid < N_NODES) g_degi[gid] = 0;              // reset for next replay
    int row = gid >> 3;
    int sub = gid & 7;
    if (row >= N_NODES) return;

    int beg = g_rowptr[row];
    int cnt = g_rowptr[row + 1] - beg;
    float acc[8] = {0.f, 0.f, 0.f, 0.f, 0.f, 0.f, 0.f, 0.f};

    auto accum = [&](uint4 v, float ws) {
        const __half2* h = reinterpret_cast<const __half2*>(&v);
        #pragma unroll
        for (int q = 0; q < 4; q++) {
            float2 f = __half22float2(h[q]);
            acc[2 * q]     += ws * f.x;
            acc[2 * q + 1] += ws * f.y;
        }
    };

    int j = 0;
    for (; j + 1 < cnt; j += 2) {
        int s0 = g_adj[beg + j + 0];
        int s1 = g_adj[beg + j + 1];
        float w0 = g_inv[s0];
        float w1 = g_inv[s1];
        uint4 v0 = reinterpret_cast<const uint4*>(x + (size_t)s0 * LATENT)[sub];
        uint4 v1 = reinterpret_cast<const uint4*>(x + (size_t)s1 * LATENT)[sub];
        accum(v0, w0); accum(v1, w1);
    }
    if (j < cnt) {
        int s0 = g_adj[beg + j];
        float w0 = g_inv[s0];
        uint4 v0 = reinterpret_cast<const uint4*>(x + (size_t)s0 * LATENT)[sub];
        accum(v0, w0);
    }

    float s = g_inv2[row];
    uint4 outp;
    __half2* oh = reinterpret_cast<__half2*>(&outp);
    #pragma unroll
    for (int q = 0; q < 4; q++)
        oh[q] = __floats2half2_rn(acc[2 * q] * s, acc[2 * q + 1] * s);
    reinterpret_cast<uint4*>(y + (size_t)row * LATENT)[sub] = outp;
}

// Layers 2..3: z_{l+1}[dst] = inv2[dst] * sum_src z_l[src]   (fp16 in/out)
__global__ void k_spmmN(const __half* __restrict__ x, __half* __restrict__ y) {
    int gid = blockIdx.x * blockDim.x + threadIdx.x;
    int row = gid >> 3;
    int sub = gid & 7;
    if (row >= N_NODES) return;

    int beg = g_rowptr[row];
    int cnt = g_rowptr[row + 1] - beg;
    float acc[8] = {0.f, 0.f, 0.f, 0.f, 0.f, 0.f, 0.f, 0.f};

    auto accum = [&](uint4 v) {
        const __half2* h = reinterpret_cast<const __half2*>(&v);
        #pragma unroll
        for (int q = 0; q < 4; q++) {
            float2 f = __half22float2(h[q]);
            acc[2 * q]     += f.x;
            acc[2 * q + 1] += f.y;
        }
    };

    int j = 0;
    for (; j + 3 < cnt; j += 4) {
        int s0 = g_adj[beg + j + 0];
        int s1 = g_adj[beg + j + 1];
        int s2 = g_adj[beg + j + 2];
        int s3 = g_adj[beg + j + 3];
        uint4 v0 = reinterpret_cast<const uint4*>(x + (size_t)s0 * LATENT)[sub];
        uint4 v1 = reinterpret_cast<const uint4*>(x + (size_t)s1 * LATENT)[sub];
        uint4 v2 = reinterpret_cast<const uint4*>(x + (size_t)s2 * LATENT)[sub];
        uint4 v3 = reinterpret_cast<const uint4*>(x + (size_t)s3 * LATENT)[sub];
        accum(v0); accum(v1); accum(v2); accum(v3);
    }
    for (; j < cnt; j++) {
        int s0 = g_adj[beg + j];
        uint4 v0 = reinterpret_cast<const uint4*>(x + (size_t)s0 * LATENT)[sub];
        accum(v0);
    }

    float s = g_inv2[row];
    uint4 outp;
    __half2* oh = reinterpret_cast<__half2*>(&outp);
    #pragma unroll
    for (int q = 0; q < 4; q++)
        oh[q] = __floats2half2_rn(acc[2 * q] * s, acc[2 * q + 1] * s);
    reinterpret_cast<uint4*>(y + (size_t)row * LATENT)[sub] = outp;
}

// Fused layer-4 + final dot. One 64-thread block per batch pair.
// z4[row][c] computed on the fly: inv2[row] * sum_{s in N(row)} z3[s][c].
// su = x0_u + sqrt(deg_u)*(z1+z2+z3+z4)[u]; gamma = su.si / 25.
__global__ void k_final(const int* __restrict__ users, const int* __restrict__ items,
                        const float* __restrict__ uemb, const float* __restrict__ iemb,
                        const __half* __restrict__ z1, const __half* __restrict__ z2,
                        const __half* __restrict__ z3,
                        float* __restrict__ out) {
    __shared__ float red[2];
    int b = blockIdx.x;
    int t = threadIdx.x;            // 0..63 = column

    int u  = users[b];
    int it = NUM_USERS + items[b];

    int bu = g_rowptr[u];
    int cu = g_rowptr[u + 1] - bu;
    int bi = g_rowptr[it];
    int ci = g_rowptr[it + 1] - bi;

    // user side
    float z4u = 0.f;
    for (int j = 0; j < cu; j++) {
        int s = g_adj[bu + j];
        z4u += __half2float(z3[(size_t)s * LATENT + t]);
    }
    z4u *= g_inv2[u];
    size_t ou = (size_t)u * LATENT + t;
    float zu = __half2float(z1[ou]) + __half2float(z2[ou]) + __half2float(z3[ou]) + z4u;
    float su = uemb[ou] + sqrtf((float)cu) * zu;

    // item side
    float z4i = 0.f;
    for (int j = 0; j < ci; j++) {
        int s = g_adj[bi + j];
        z4i += __half2float(z3[(size_t)s * LATENT + t]);
    }
    z4i *= g_inv2[it];
    size_t oi = (size_t)it * LATENT + t;
    float zi = __half2float(z1[oi]) + __half2float(z2[oi]) + __half2float(z3[oi]) + z4i;
    float si = iemb[(size_t)(it - NUM_USERS) * LATENT + t] + sqrtf((float)ci) * zi;

    // block dot over 64 values (2 warps)
    float dot = su * si;
    #pragma unroll
    for (int off = 16; off > 0; off >>= 1)
        dot += __shfl_xor_sync(0xffffffffu, dot, off);
    if ((t & 31) == 0) red[t >> 5] = dot;
    __syncthreads();
    if (t == 0) out[b] = (red[0] + red[1]) * (1.0f / 25.0f);
}

// ---------------- launch ----------------------------------------------------
extern "C" void kernel_launch(void* const* d_in, const int* in_sizes, int n_in,
                              void* d_out, int out_size) {
    const int*   users = (const int*)  d_in[0];
    const int*   items = (const int*)  d_in[1];
    const int*   eu    = (const int*)  d_in[2];
    const int*   ei    = (const int*)  d_in[3];
    const float* uemb  = (const float*)d_in[4];
    const float* iemb  = (const float*)d_in[5];
    float*       out   = (float*)d_out;

    const int T = 256;
    const int n8     = TOT_F / 8;                    // 1.2M
    const int gBig   = (n8 + T - 1) / T;
    const int gEdge  = (N_EDGES + T - 1) / T;
    const int gRow8  = (N_NODES * 8 + T - 1) / T;

    static __half* pZ = nullptr; static __half* pX = nullptr;
    if (!pZ) { cudaGetSymbolAddress((void**)&pZ, g_z);
               cudaGetSymbolAddress((void**)&pX, g_x0h); }
    __half* z1 = pZ;
    __half* z2 = pZ + (size_t)TOT_F;
    __half* z3 = pZ + (size_t)2 * TOT_F;

    // setup: deg atomics + fp16 cast fused, then CSR build
    k_deg_conv<<<gBig, T>>>(eu, ei, uemb, iemb);
    k_inv_part<<<N_PART, 256>>>();
    k_rowptr  <<<N_PART, 256>>>();
    k_fill    <<<gEdge, T>>>(eu, ei);

    // layers 1..3 materialized (fp16 storage, fp32 accumulation)
    k_spmm1h<<<gRow8, T>>>(pX, z1);
    k_spmmN <<<gRow8, T>>>(z1, z2);
    k_spmmN <<<gRow8, T>>>(z2, z3);

    // layer 4 fused into final (only batch rows needed)
    k_final<<<BATCH, 64>>>(users, items, uemb, iemb, z1, z2, z3, out);
}